// round 1
// baseline (speedup 1.0000x reference)
#include <cuda_runtime.h>
#include <math.h>

#define MAXN   4096
#define CC     128
#define HH     4
#define DD     32
#define MAXNBR 1024
#define ROWS   8

// ---- scratch (device globals; no allocation allowed) ----
__device__ unsigned long long g_mask[(size_t)MAXN * MAXN / 64];   // 2 MB adjacency bitmask
__device__ float g_q[MAXN * CC];
__device__ float g_k[MAXN * CC];
__device__ float g_v[MAXN * CC];
__device__ float g_att[MAXN * CC];
__device__ float g_wqT[CC * CC], g_wkT[CC * CC], g_wvT[CC * CC], g_woT[CC * CC];
__device__ int   g_is64;

// Detect whether edge_index arrived as int64 or int32.
// First N entries of both rows are self loops 0..N-1. Viewed as int32:
//   int32 data: [0,1,2,3,...]  -> ei[1]==1 && ei[3]==3
//   int64 data: [0,0,1,0,2,0,] -> ei[1]==0 && ei[3]==0
__global__ void detect_dtype(const int* ei) {
    if (threadIdx.x == 0)
        g_is64 = (ei[1] == 1 && ei[3] == 3) ? 0 : 1;
}

__global__ void zero_mask(int nwords) {
    int i = blockIdx.x * blockDim.x + threadIdx.x;
    int stride = gridDim.x * blockDim.x;
    for (; i < nwords; i += stride) g_mask[i] = 0ull;
}

__global__ void build_mask(const int* ei, int E, int W) {
    int e = blockIdx.x * blockDim.x + threadIdx.x;
    if (e >= E) return;
    int r, c;
    if (g_is64) {
        const long long* p = (const long long*)ei;
        r = (int)p[e];
        c = (int)p[E + e];
    } else {
        r = ei[e];
        c = ei[E + e];
    }
    atomicOr(&g_mask[(size_t)r * W + (c >> 6)], 1ull << (c & 63));
}

__global__ void transpose_w(const float* wq, const float* wk, const float* wv, const float* wo) {
    int i = blockIdx.x * blockDim.x + threadIdx.x;
    if (i >= CC * CC) return;
    int r = i / CC, c = i % CC;
    g_wqT[c * CC + r] = wq[i];
    g_wkT[c * CC + r] = wk[i];
    g_wvT[c * CC + r] = wv[i];
    g_woT[c * CC + r] = wo[i];
}

// QKV projection: 8 rows per block, 128 threads (thread = output channel).
__global__ void qkv_kernel(const float* __restrict__ x,
                           const float* __restrict__ bq,
                           const float* __restrict__ bk,
                           const float* __restrict__ bv) {
    int t = threadIdx.x;
    int n0 = blockIdx.x * ROWS;
    __shared__ float xs[ROWS][CC];
#pragma unroll
    for (int r = 0; r < ROWS; r++) xs[r][t] = x[(n0 + r) * CC + t];
    __syncthreads();

    float aq[ROWS], ak[ROWS], av[ROWS];
    float bqv = bq[t], bkv = bk[t], bvv = bv[t];
#pragma unroll
    for (int r = 0; r < ROWS; r++) { aq[r] = bqv; ak[r] = bkv; av[r] = bvv; }

    for (int k = 0; k < CC; k++) {
        float wqv = g_wqT[k * CC + t];
        float wkv = g_wkT[k * CC + t];
        float wvv = g_wvT[k * CC + t];
#pragma unroll
        for (int r = 0; r < ROWS; r++) {
            float xv = xs[r][k];
            aq[r] += xv * wqv;
            ak[r] += xv * wkv;
            av[r] += xv * wvv;
        }
    }
#pragma unroll
    for (int r = 0; r < ROWS; r++) {
        g_q[(n0 + r) * CC + t] = aq[r];
        g_k[(n0 + r) * CC + t] = ak[r];
        g_v[(n0 + r) * CC + t] = av[r];
    }
}

// Sparse attention: block per node; warp per head; lane per head-dim.
__global__ void attn_kernel(int N) {
    int n = blockIdx.x;
    int t = threadIdx.x;
    int lane = t & 31, warp = t >> 5;
    int W = N >> 6;   // 64-bit words per mask row

    __shared__ unsigned long long words[64];
    __shared__ int cnts[64];
    __shared__ int offs[64];
    __shared__ int total_s;
    __shared__ int nbr[MAXNBR];
    __shared__ float sc[HH][MAXNBR];

    if (t < W) {
        unsigned long long w = g_mask[(size_t)n * W + t];
        words[t] = w;
        cnts[t] = __popcll(w);
    }
    __syncthreads();
    if (t == 0) {
        int run = 0;
        for (int i = 0; i < W; i++) { offs[i] = run; run += cnts[i]; }
        total_s = run > MAXNBR ? MAXNBR : run;
    }
    __syncthreads();
    if (t < W) {
        int off = offs[t];
        unsigned long long w = words[t];
        while (w) {
            int b = __ffsll((long long)w) - 1;
            w &= w - 1;
            if (off < MAXNBR) nbr[off] = (t << 6) + b;
            off++;
        }
    }
    __syncthreads();
    int total = total_s;

    // scores: q . k for each neighbor (deterministic order, warp-reduce)
    const float scale = 0.17677669529663687f;   // 1/sqrt(32)
    float qv = g_q[n * CC + warp * DD + lane] * scale;
    for (int j = 0; j < total; j++) {
        float p = qv * g_k[nbr[j] * CC + warp * DD + lane];
#pragma unroll
        for (int o = 16; o; o >>= 1) p += __shfl_xor_sync(0xffffffffu, p, o);
        if (lane == 0) sc[warp][j] = p;
    }
    __syncwarp();

    // softmax (max, exp, sum)
    float mx = -1e30f;
    for (int j = lane; j < total; j += 32) mx = fmaxf(mx, sc[warp][j]);
#pragma unroll
    for (int o = 16; o; o >>= 1) mx = fmaxf(mx, __shfl_xor_sync(0xffffffffu, mx, o));
    float s = 0.f;
    for (int j = lane; j < total; j += 32) {
        float e = __expf(sc[warp][j] - mx);
        sc[warp][j] = e;
        s += e;
    }
#pragma unroll
    for (int o = 16; o; o >>= 1) s += __shfl_xor_sync(0xffffffffu, s, o);
    __syncwarp();

    // weighted V accumulation (lane = dim, coalesced gathers)
    float acc = 0.f;
    for (int j = 0; j < total; j++)
        acc += sc[warp][j] * g_v[nbr[j] * CC + warp * DD + lane];

    g_att[n * CC + warp * DD + lane] = acc / s;
}

// Output projection + residual + LayerNorm; 8 rows per block.
__global__ void out_ln_kernel(const float* __restrict__ x,
                              const float* __restrict__ bo,
                              const float* __restrict__ gamma,
                              const float* __restrict__ beta,
                              float* __restrict__ out) {
    int t = threadIdx.x;
    int lane = t & 31, warp = t >> 5;
    int n0 = blockIdx.x * ROWS;
    __shared__ float as[ROWS][CC];
#pragma unroll
    for (int r = 0; r < ROWS; r++) as[r][t] = g_att[(n0 + r) * CC + t];
    __syncthreads();

    float acc[ROWS];
    float bov = bo[t];
#pragma unroll
    for (int r = 0; r < ROWS; r++) acc[r] = bov;
    for (int k = 0; k < CC; k++) {
        float wv = g_woT[k * CC + t];
#pragma unroll
        for (int r = 0; r < ROWS; r++) acc[r] += as[r][k] * wv;
    }

    float y[ROWS];
#pragma unroll
    for (int r = 0; r < ROWS; r++) y[r] = x[(n0 + r) * CC + t] + acc[r];

    __shared__ float red[4];
    float gv = gamma[t], bv = beta[t];
#pragma unroll
    for (int r = 0; r < ROWS; r++) {
        float v = y[r];
        float s = v;
#pragma unroll
        for (int o = 16; o; o >>= 1) s += __shfl_xor_sync(0xffffffffu, s, o);
        if (lane == 0) red[warp] = s;
        __syncthreads();
        float mu = (red[0] + red[1] + red[2] + red[3]) * (1.0f / CC);
        __syncthreads();
        float d = v - mu;
        float s2 = d * d;
#pragma unroll
        for (int o = 16; o; o >>= 1) s2 += __shfl_xor_sync(0xffffffffu, s2, o);
        if (lane == 0) red[warp] = s2;
        __syncthreads();
        float var = (red[0] + red[1] + red[2] + red[3]) * (1.0f / CC);
        __syncthreads();
        out[(n0 + r) * CC + t] = d * rsqrtf(var + 1e-5f) * gv + bv;
    }
}

extern "C" void kernel_launch(void* const* d_in, const int* in_sizes, int n_in,
                              void* d_out, int out_size) {
    const float* x     = (const float*)d_in[0];
    const int*   ei    = (const int*)d_in[1];
    const float* wq    = (const float*)d_in[2];
    const float* bq    = (const float*)d_in[3];
    const float* wk    = (const float*)d_in[4];
    const float* bk    = (const float*)d_in[5];
    const float* wv    = (const float*)d_in[6];
    const float* bv    = (const float*)d_in[7];
    const float* wo    = (const float*)d_in[8];
    const float* bo    = (const float*)d_in[9];
    const float* gamma = (const float*)d_in[10];
    const float* beta  = (const float*)d_in[11];

    int N = in_sizes[0] / CC;
    int E = in_sizes[1] / 2;
    int W = N / 64;                 // mask words per row
    int nwords = N * W;

    detect_dtype<<<1, 1>>>(ei);
    zero_mask<<<256, 256>>>(nwords);
    build_mask<<<(E + 255) / 256, 256>>>(ei, E, W);
    transpose_w<<<(CC * CC + 255) / 256, 256>>>(wq, wk, wv, wo);
    qkv_kernel<<<N / ROWS, CC>>>(x, bq, bk, bv);
    attn_kernel<<<N, CC>>>(N);
    out_ln_kernel<<<N / ROWS, CC>>>(x, bo, gamma, beta, (float*)d_out);
}